// round 8
// baseline (speedup 1.0000x reference)
#include <cuda_runtime.h>

// ---------------- problem constants ----------------
#define TDIM   2048
#define BDIM   16384
#define NTS    18431            // TDIM + BDIM - 1
#define MQ     24               // seasonality period == HORIZON
#define XOUT_N (BDIM * TDIM)    // 33554432
#define DEN_N  (BDIM * 48)      // 786432

// ---------------- chunk-parallel scan config ----------------
#define W_UP   1440             // warm-up steps (60 seasonal cycles)
#define WMACRO (W_UP / MQ)      // 60
#define CH_S   19               // output steps per chunk
#define WPB    4                // warps per block
#define CPB    (2 * WPB)        // chunks per block (2 per warp, interleaved)
#define K_BT   (WPB * 32)       // 128 threads
#define K_NB   122              // 122*8 = 976 chunk slots >= 971 needed
#define NCHUNK 1024             // logical chunk-index space
#define BSPAN  (CPB * CH_S)     // 152 output steps per block
#define SLICE  (W_UP + BSPAN)   // 1592 ts floats used
#define SLICEP (SLICE + 32)     // pad: lanes 19..31 of last macro overread

#define XB     (XOUT_N / 4 / 256)        // 32768 xout blocks
#define DB     ((DEN_N + 255) / 256)     // 3072 denorm blocks

// ---------------- device scratch (no allocs allowed) ----------------
__device__ __align__(16) float g_xn[18448];   // padded for float4 reads
__device__ float g_l [NTS];
__device__ float g_s [NTS];
__device__ float g_lstart[NCHUNK];
__device__ float g_lend  [NCHUNK];
__device__ float g_c     [NCHUNK];

__device__ __forceinline__ float frcp(float x) {
    float r;
    asm("rcp.approx.ftz.f32 %0, %1;" : "=f"(r) : "f"(x));
    return r;
}

// generic (activity-masked) affine-scan macro: handles partially-clamped
// and fully-dead macros. Used <=2 iterations per clamped warp.
__device__ __forceinline__ void macro_generic(
    float y, int u, int lane, float& q, float& iq, float& l,
    float a, float g, float ka, float kg)
{
    bool  act = (u >= 0);
    float r   = y * iq;
    float Av  = act ? ka    : 1.0f;
    float Bv  = act ? a * r : 0.0f;
#pragma unroll
    for (int s = 1; s < MQ; s <<= 1) {
        float Bp = __shfl_up_sync(0xffffffffu, Bv, s);
        float Ap = __shfl_up_sync(0xffffffffu, Av, s);
        if (lane >= s) { Bv = fmaf(Av, Bp, Bv); Av *= Ap; }
    }
    float ll = fmaf(Av, l, Bv);
    if (act) {
        float il = frcp(ll);
        float sn = fmaf(kg, q, (g * y) * il);
        q  = sn;
        iq = frcp(sn);
    }
    l = __shfl_sync(0xffffffffu, ll, MQ - 1);
}

// ============ K1: dual-chunk interleaved lane-per-slot warp scan ============
// One warp = TWO adjacent 19-step chunks; their independent macro chains are
// interleaved instruction-by-instruction so each fills the other's shfl/rcp
// latency. Lane j owns seasonal slot j. Level chain solved per macro by a
// Kogge-Stone affine scan.
__global__ __launch_bounds__(K_BT) void k_scan(
    const float* __restrict__ x,
    const float* __restrict__ alpha_p, const float* __restrict__ gamma_p,
    const float* __restrict__ inits,   const float* __restrict__ level_p)
{
    __shared__ float sm_ts[SLICEP];
    __shared__ float sm_xn[BSPAN];
    __shared__ float sm_l [BSPAN];
    __shared__ float sm_s [BSPAN];

    const int tid        = threadIdx.x;
    const int wid        = tid >> 5;
    const int lane       = tid & 31;
    const int blk_t0     = blockIdx.x * BSPAN;
    const int slice_base = blk_t0 - W_UP;

    // stage ts slice: ts[u] = (u < T) ? x[0,u,0] : x[u-T+1, T-1, 0]
    for (int idx = tid; idx < SLICEP; idx += K_BT) {
        int u = slice_base + idx;
        float v = 1.0f;
        if (u >= 0 && u < NTS)
            v = (u < TDIM) ? x[u] : x[(u - (TDIM - 1)) * TDIM + (TDIM - 1)];
        sm_ts[idx] = v;
    }
    __syncthreads();

    const float a  = *alpha_p;
    const float g  = *gamma_p;
    const float ka = 1.0f - a;
    const float kg = 1.0f - g;
    const float ka2 = ka * ka, ka4 = ka2 * ka2, ka8 = ka4 * ka4, ka16 = ka8 * ka8;

    const int clA   = 2 * wid;                 // chunk-local indices
    const int clB   = 2 * wid + 1;
    const int chA   = blockIdx.x * CPB + clA;
    const int chB   = chA + 1;
    const int t0A   = chA * CH_S;
    const int t0B   = chB * CH_S;
    const int u0A   = t0A - W_UP;
    const int u0B   = t0B - W_UP;
    const int baseA = clA * CH_S;              // sm_ts offset of chunk A's u0
    const int baseB = clB * CH_S;

    // per-lane constant ka^(lane+1)
    float kaPow = ka;
    for (int i = 0; i < lane; i++) kaPow *= ka;

    // lane j owns slot j: q = inits[(j + t0) % 24]
    float qA = inits[(lane + t0A) % MQ];
    float qB = inits[(lane + t0B) % MQ];
    float iqA = frcp(qA), iqB = frcp(qB);
    float lA = *level_p,  lB = lA;

    // skip macros fully dead for BOTH chunks (B activates first since u0B>u0A)
    int kkstart = (u0B < 0) ? ((-u0B) / MQ) : 0;

    for (int kk = kkstart; kk < WMACRO; kk++) {
        if (u0A + kk * MQ >= 0) {
            // ---- dual fast path: both chunks fully active ----
            float yA = sm_ts[baseA + kk * MQ + lane];
            float yB = sm_ts[baseB + kk * MQ + lane];
            float rA = yA * iqA,      rB = yB * iqB;
            float BA = a * rA,        BB = a * rB;
            float Bp, Bq;
            Bp = __shfl_up_sync(0xffffffffu, BA, 1);
            Bq = __shfl_up_sync(0xffffffffu, BB, 1);
            if (lane >= 1)  { BA = fmaf(ka,   Bp, BA); BB = fmaf(ka,   Bq, BB); }
            Bp = __shfl_up_sync(0xffffffffu, BA, 2);
            Bq = __shfl_up_sync(0xffffffffu, BB, 2);
            if (lane >= 2)  { BA = fmaf(ka2,  Bp, BA); BB = fmaf(ka2,  Bq, BB); }
            Bp = __shfl_up_sync(0xffffffffu, BA, 4);
            Bq = __shfl_up_sync(0xffffffffu, BB, 4);
            if (lane >= 4)  { BA = fmaf(ka4,  Bp, BA); BB = fmaf(ka4,  Bq, BB); }
            Bp = __shfl_up_sync(0xffffffffu, BA, 8);
            Bq = __shfl_up_sync(0xffffffffu, BB, 8);
            if (lane >= 8)  { BA = fmaf(ka8,  Bp, BA); BB = fmaf(ka8,  Bq, BB); }
            Bp = __shfl_up_sync(0xffffffffu, BA, 16);
            Bq = __shfl_up_sync(0xffffffffu, BB, 16);
            if (lane >= 16) { BA = fmaf(ka16, Bp, BA); BB = fmaf(ka16, Bq, BB); }
            float llA = fmaf(kaPow, lA, BA);
            float llB = fmaf(kaPow, lB, BB);
            float ilA = frcp(llA),     ilB = frcp(llB);
            float snA = fmaf(kg, qA, (g * yA) * ilA);
            float snB = fmaf(kg, qB, (g * yB) * ilB);
            qA = snA;  iqA = frcp(snA);
            qB = snB;  iqB = frcp(snB);
            lA = __shfl_sync(0xffffffffu, llA, MQ - 1);
            lB = __shfl_sync(0xffffffffu, llB, MQ - 1);
        } else {
            // ---- slow path: <=2 iterations per clamped warp ----
            float yA = sm_ts[baseA + kk * MQ + lane];
            float yB = sm_ts[baseB + kk * MQ + lane];
            macro_generic(yA, u0A + kk * MQ + lane, lane, qA, iqA, lA, a, g, ka, kg);
            macro_generic(yB, u0B + kk * MQ + lane, lane, qB, iqB, lB, a, g, ka, kg);
        }
    }

    if (lane == 0) { g_lstart[chA] = lA; g_lstart[chB] = lB; }

    // ---- output phase: one dual fast macro; lanes 0..18 produce results ----
    {
        float yA = sm_ts[baseA + WMACRO * MQ + lane];
        float yB = sm_ts[baseB + WMACRO * MQ + lane];
        float rA = yA * iqA,      rB = yB * iqB;
        float BA = a * rA,        BB = a * rB;
        float Bp, Bq;
        Bp = __shfl_up_sync(0xffffffffu, BA, 1);
        Bq = __shfl_up_sync(0xffffffffu, BB, 1);
        if (lane >= 1)  { BA = fmaf(ka,   Bp, BA); BB = fmaf(ka,   Bq, BB); }
        Bp = __shfl_up_sync(0xffffffffu, BA, 2);
        Bq = __shfl_up_sync(0xffffffffu, BB, 2);
        if (lane >= 2)  { BA = fmaf(ka2,  Bp, BA); BB = fmaf(ka2,  Bq, BB); }
        Bp = __shfl_up_sync(0xffffffffu, BA, 4);
        Bq = __shfl_up_sync(0xffffffffu, BB, 4);
        if (lane >= 4)  { BA = fmaf(ka4,  Bp, BA); BB = fmaf(ka4,  Bq, BB); }
        Bp = __shfl_up_sync(0xffffffffu, BA, 8);
        Bq = __shfl_up_sync(0xffffffffu, BB, 8);
        if (lane >= 8)  { BA = fmaf(ka8,  Bp, BA); BB = fmaf(ka8,  Bq, BB); }
        Bp = __shfl_up_sync(0xffffffffu, BA, 16);
        Bq = __shfl_up_sync(0xffffffffu, BB, 16);
        if (lane >= 16) { BA = fmaf(ka16, Bp, BA); BB = fmaf(ka16, Bq, BB); }
        float llA = fmaf(kaPow, lA, BA);
        float llB = fmaf(kaPow, lB, BB);
        float ilA = frcp(llA),     ilB = frcp(llB);
        float snA = fmaf(kg, qA, (g * yA) * ilA);
        float snB = fmaf(kg, qB, (g * yB) * ilB);
        if (lane < CH_S) {
            sm_xn[baseA + lane] = rA * ilA;
            sm_l [baseA + lane] = llA;
            sm_s [baseA + lane] = snA;
            sm_xn[baseB + lane] = rB * ilB;
            sm_l [baseB + lane] = llB;
            sm_s [baseB + lane] = snB;
        }
        float leA = __shfl_sync(0xffffffffu, llA, CH_S - 1);
        float leB = __shfl_sync(0xffffffffu, llB, CH_S - 1);
        if (lane == 0) { g_lend[chA] = leA; g_lend[chB] = leB; }
    }

    __syncthreads();
    int span = NTS - blk_t0; if (span > BSPAN) span = BSPAN;
    for (int idx = tid; idx < span; idx += K_BT) {
        g_xn[blk_t0 + idx] = sm_xn[idx];
        g_l [blk_t0 + idx] = sm_l [idx];
        g_s [blk_t0 + idx] = sm_s [idx];
    }
}

// ============ K2: prefix product of boundary ratios -> g_c only ============
// ratio_k = lstart_k / lend_{k-1} = c_k / c_{k-1}; c_0 = 1 (exact start).
// xn is symmetry-invariant; l,s corrected at consumption time in k_out.
__global__ __launch_bounds__(NCHUNK) void k_prefix() {
    __shared__ float c[NCHUNK];
    int k = threadIdx.x;
    float ratio = 1.0f;
    if (k > 0 && k * CH_S < NTS) ratio = g_lstart[k] / g_lend[k - 1];
    c[k] = ratio;
    __syncthreads();
    for (int o = 1; o < NCHUNK; o <<= 1) {
        float v = (k >= o) ? c[k - o] : 1.0f;
        __syncthreads();
        c[k] *= v;
        __syncthreads();
    }
    g_c[k] = c[k];
}

// ============ K3: fused x_out + denorm (correction applied here) ============
__global__ void k_out(float* __restrict__ out) {
    int bx = blockIdx.x;
    if (bx < XB) {
        int i4   = bx * blockDim.x + threadIdx.x;
        int i    = i4 << 2;
        int b    = i >> 11;
        int t    = i & (TDIM - 1);
        int base = b + t;
        int qq   = base >> 2;
        int sh   = base & 3;
        const float4* xn4 = reinterpret_cast<const float4*>(g_xn);
        float4 f0 = xn4[qq];
        float4 v;
        if (sh == 0) {
            v = f0;
        } else {
            float4 f1 = xn4[qq + 1];
            if (sh == 1)      v = make_float4(f0.y, f0.z, f0.w, f1.x);
            else if (sh == 2) v = make_float4(f0.z, f0.w, f1.x, f1.y);
            else              v = make_float4(f0.w, f1.x, f1.y, f1.z);
        }
        reinterpret_cast<float4*>(out)[i4] = v;
    } else {
        int i = (bx - XB) * blockDim.x + threadIdx.x;
        if (i < DEN_N) {
            int b = i / 48;
            int r = i - b * 48;
            int h = r >> 1;
            float v;
            if (r & 1) {
                int t = (TDIM - MQ) + b + h;
                v = g_s[t] * g_c[t / CH_S];          // s_true = s * c
            } else {
                int t = (TDIM - 1) + b;
                v = g_l[t] / g_c[t / CH_S];          // l_true = l / c
            }
            out[XOUT_N + i] = v;
        }
    }
}

extern "C" void kernel_launch(void* const* d_in, const int* in_sizes, int n_in,
                              void* d_out, int out_size) {
    const float* x     = (const float*)d_in[0];
    const float* alpha = (const float*)d_in[1];
    const float* gamma = (const float*)d_in[2];
    const float* inits = (const float*)d_in[3];
    const float* level = (const float*)d_in[4];
    float* out = (float*)d_out;

    k_scan<<<K_NB, K_BT>>>(x, alpha, gamma, inits, level);
    k_prefix<<<1, NCHUNK>>>();
    int nb = (out_size >= XOUT_N + DEN_N) ? (XB + DB) : XB;
    k_out<<<nb, 256>>>(out);
}

// round 9
// speedup vs baseline: 1.1878x; 1.1878x over previous
#include <cuda_runtime.h>

// ---------------- problem constants ----------------
#define TDIM   2048
#define BDIM   16384
#define NTS    18431            // TDIM + BDIM - 1
#define MQ     24               // seasonality period == HORIZON
#define XOUT_N (BDIM * TDIM)    // 33554432
#define DEN_N  (BDIM * 48)      // 786432

// ---------------- chunk-parallel scan config (R7 layout) ----------------
#define W_UP   1440             // warm-up steps (60 seasonal cycles)
#define WMACRO (W_UP / MQ)      // 60
#define CH_S   19               // output steps per chunk
#define WPB    4                // warps (=chunks) per block
#define K3_BT  (WPB * 32)       // 128 threads
#define K3_NB  243              // 972 chunk slots >= 971 needed
#define NCHUNK 1024             // logical chunk-index space
#define BSPAN  (WPB * CH_S)     // 76 output steps per block
#define SLICE  (W_UP + BSPAN)   // 1516 ts floats used
#define SLICEP (SLICE + 32)     // pad: last-macro lanes 19..31 overread

#define XB     (XOUT_N / 4 / 256)        // 32768 xout blocks
#define DB     ((DEN_N + 255) / 256)     // 3072 denorm blocks
#define SHN    18436                     // shifted-copy element count

// ---------------- device scratch (no allocs allowed) ----------------
__device__ __align__(16) float g_xn[18448];        // padded
__device__ __align__(16) float g_xnsh[4][18448];   // 4 shifted copies of xn
__device__ float g_l [NTS];
__device__ float g_s [NTS];
__device__ float g_lstart[NCHUNK];
__device__ float g_lend  [NCHUNK];
__device__ float g_c     [NCHUNK];

__device__ __forceinline__ float frcp(float x) {
    float r;
    asm("rcp.approx.ftz.f32 %0, %1;" : "=f"(r) : "f"(x));
    return r;
}

// ============ K1: lane-per-slot warp-parallel ES scan (R7 numerics) ========
// One warp = one 19-step chunk warm-started 1440 steps back. Lane j owns
// seasonal slot j. Level chain solved per 24-step macro by a Kogge-Stone
// affine scan; next macro's y is prefetched so the LDS is off the chain.
__global__ __launch_bounds__(K3_BT) void k_scan(
    const float* __restrict__ x,
    const float* __restrict__ alpha_p, const float* __restrict__ gamma_p,
    const float* __restrict__ inits,   const float* __restrict__ level_p)
{
    __shared__ float sm_ts[SLICEP];
    __shared__ float sm_xn[BSPAN];
    __shared__ float sm_l [BSPAN];
    __shared__ float sm_s [BSPAN];

    const int tid        = threadIdx.x;
    const int wid        = tid >> 5;
    const int lane       = tid & 31;
    const int blk_t0     = blockIdx.x * BSPAN;
    const int slice_base = blk_t0 - W_UP;

    // stage ts slice: ts[u] = (u < T) ? x[0,u,0] : x[u-T+1, T-1, 0]
    for (int idx = tid; idx < SLICEP; idx += K3_BT) {
        int u = slice_base + idx;
        float v = 1.0f;
        if (u >= 0 && u < NTS)
            v = (u < TDIM) ? x[u] : x[(u - (TDIM - 1)) * TDIM + (TDIM - 1)];
        sm_ts[idx] = v;
    }
    __syncthreads();

    const float a  = *alpha_p;
    const float g  = *gamma_p;
    const float ka = 1.0f - a;
    const float kg = 1.0f - g;
    const float ka2 = ka * ka, ka4 = ka2 * ka2, ka8 = ka4 * ka4, ka16 = ka8 * ka8;

    const int chunk = blockIdx.x * WPB + wid;
    const int t0    = chunk * CH_S;
    const int u0    = t0 - W_UP;
    const int base  = wid * CH_S;      // sm_ts index of this warp's u0

    // per-lane constant ka^(lane+1)
    float kaPow = ka;
    for (int i = 0; i < lane; i++) kaPow *= ka;

    // lane j owns slot j: q = inits[(j + t0) % 24]
    float q, iq;
    {
        int idx = (lane + t0) % MQ;
        q  = inits[idx];
        iq = frcp(q);
    }
    float l = *level_p;

    int kk = 0;
    // ---- clamped prefix (chunks with t0 < W_UP): skip whole macros; one
    // partial macro where lanes j < rem use identity affines & skip updates.
    if (u0 < 0) {
        int m   = (-u0) / MQ;
        int rem = (-u0) % MQ;
        kk = m;
        if (rem > 0) {
            int off = base + kk * MQ;
            float y = sm_ts[off + lane];
            float r = y * iq;
            bool act = (lane >= rem);
            float Av = act ? ka      : 1.0f;
            float Bv = act ? a * r   : 0.0f;
#pragma unroll
            for (int s = 1; s < MQ; s <<= 1) {
                float Bp = __shfl_up_sync(0xffffffffu, Bv, s);
                float Ap = __shfl_up_sync(0xffffffffu, Av, s);
                if (lane >= s) { Bv = fmaf(Av, Bp, Bv); Av *= Ap; }
            }
            float ll = fmaf(Av, l, Bv);
            if (act) {
                float il = frcp(ll);
                float sn = fmaf(kg, q, (g * y) * il);
                q  = sn;
                iq = frcp(sn);
            }
            l = __shfl_sync(0xffffffffu, ll, MQ - 1);
            kk++;
        }
    }

    // ---- clean warm loop with y-prefetch (LDS off the dependency chain) ----
    float y = sm_ts[base + kk * MQ + lane];
    for (; kk < WMACRO; kk++) {
        float ynx = sm_ts[base + (kk + 1) * MQ + lane];  // next macro / output
        float r = y * iq;
        float B = a * r;
        float Bp;
        Bp = __shfl_up_sync(0xffffffffu, B, 1);  if (lane >= 1)  B = fmaf(ka,   Bp, B);
        Bp = __shfl_up_sync(0xffffffffu, B, 2);  if (lane >= 2)  B = fmaf(ka2,  Bp, B);
        Bp = __shfl_up_sync(0xffffffffu, B, 4);  if (lane >= 4)  B = fmaf(ka4,  Bp, B);
        Bp = __shfl_up_sync(0xffffffffu, B, 8);  if (lane >= 8)  B = fmaf(ka8,  Bp, B);
        Bp = __shfl_up_sync(0xffffffffu, B, 16); if (lane >= 16) B = fmaf(ka16, Bp, B);
        float ll = fmaf(kaPow, l, B);
        float il = frcp(ll);
        float sn = fmaf(kg, q, (g * y) * il);
        q  = sn;
        iq = frcp(sn);
        l  = __shfl_sync(0xffffffffu, ll, MQ - 1);
        y  = ynx;
    }

    if (lane == 0) g_lstart[chunk] = l;    // level entering t0

    // ---- output phase: 19 steps (lanes 0..18 produce results) ----
    {
        float r = y * iq;
        float B = a * r;
        float Bp;
        Bp = __shfl_up_sync(0xffffffffu, B, 1);  if (lane >= 1)  B = fmaf(ka,   Bp, B);
        Bp = __shfl_up_sync(0xffffffffu, B, 2);  if (lane >= 2)  B = fmaf(ka2,  Bp, B);
        Bp = __shfl_up_sync(0xffffffffu, B, 4);  if (lane >= 4)  B = fmaf(ka4,  Bp, B);
        Bp = __shfl_up_sync(0xffffffffu, B, 8);  if (lane >= 8)  B = fmaf(ka8,  Bp, B);
        Bp = __shfl_up_sync(0xffffffffu, B, 16); if (lane >= 16) B = fmaf(ka16, Bp, B);
        float ll = fmaf(kaPow, l, B);
        float il = frcp(ll);
        float sn = fmaf(kg, q, (g * y) * il);
        if (lane < CH_S) {
            int oo = base + lane;
            sm_xn[oo] = r * il;
            sm_l [oo] = ll;
            sm_s [oo] = sn;
        }
        float le = __shfl_sync(0xffffffffu, ll, CH_S - 1);
        if (lane == 0) g_lend[chunk] = le;   // level entering t0 + 19
    }

    __syncthreads();
    int span = NTS - blk_t0; if (span > BSPAN) span = BSPAN;
    for (int idx = tid; idx < span; idx += K3_BT) {
        g_xn[blk_t0 + idx] = sm_xn[idx];
        g_l [blk_t0 + idx] = sm_l [idx];
        g_s [blk_t0 + idx] = sm_s [idx];
    }
}

// ============ K2 (fused): prefix product + shifted-copy build ============
// block 0: c_k prefix product of boundary ratios -> g_c (c_0 = 1).
// blocks 1..: g_xnsh[s][i] = xn[i+s] so k_out can do 1 aligned LDG.128/float4.
__global__ __launch_bounds__(1024) void k_mid() {
    if (blockIdx.x == 0) {
        __shared__ float c[NCHUNK];
        int k = threadIdx.x;
        float ratio = 1.0f;
        if (k > 0 && k * CH_S < NTS) ratio = g_lstart[k] / g_lend[k - 1];
        c[k] = ratio;
        __syncthreads();
        for (int o = 1; o < NCHUNK; o <<= 1) {
            float v = (k >= o) ? c[k - o] : 1.0f;
            __syncthreads();
            c[k] *= v;
            __syncthreads();
        }
        g_c[k] = c[k];
    } else {
        int i = (blockIdx.x - 1) * 1024 + threadIdx.x;
        if (i < SHN) {
            float v0 = g_xn[i];
            float v1 = g_xn[i + 1];
            float v2 = g_xn[i + 2];
            float v3 = g_xn[i + 3];
            g_xnsh[0][i] = v0;
            g_xnsh[1][i] = v1;
            g_xnsh[2][i] = v2;
            g_xnsh[3][i] = v3;
        }
    }
}

// ============ K3: fused x_out + denorm ============
// x_out: exactly 1 aligned LDG.128 (from the sh-shifted copy; sh is
// warp-uniform) + 1 STG.128 per 16 output bytes.
__global__ void k_out(float* __restrict__ out) {
    int bx = blockIdx.x;
    if (bx < XB) {
        int i4   = bx * blockDim.x + threadIdx.x;
        int i    = i4 << 2;
        int b    = i >> 11;
        int t    = i & (TDIM - 1);
        int base = b + t;
        int qq   = base >> 2;
        int sh   = base & 3;
        const float4* p = reinterpret_cast<const float4*>(g_xnsh[sh]);
        reinterpret_cast<float4*>(out)[i4] = p[qq];
    } else {
        int i = (bx - XB) * blockDim.x + threadIdx.x;
        if (i < DEN_N) {
            int b = i / 48;
            int r = i - b * 48;
            int h = r >> 1;
            float v;
            if (r & 1) {
                int t = (TDIM - MQ) + b + h;
                v = g_s[t] * g_c[t / CH_S];          // s_true = s * c
            } else {
                int t = (TDIM - 1) + b;
                v = g_l[t] / g_c[t / CH_S];          // l_true = l / c
            }
            out[XOUT_N + i] = v;
        }
    }
}

extern "C" void kernel_launch(void* const* d_in, const int* in_sizes, int n_in,
                              void* d_out, int out_size) {
    const float* x     = (const float*)d_in[0];
    const float* alpha = (const float*)d_in[1];
    const float* gamma = (const float*)d_in[2];
    const float* inits = (const float*)d_in[3];
    const float* level = (const float*)d_in[4];
    float* out = (float*)d_out;

    k_scan<<<K3_NB, K3_BT>>>(x, alpha, gamma, inits, level);
    k_mid<<<1 + (SHN + 1023) / 1024, 1024>>>();
    int nb = (out_size >= XOUT_N + DEN_N) ? (XB + DB) : XB;
    k_out<<<nb, 256>>>(out);
}